// round 3
// baseline (speedup 1.0000x reference)
#include <cuda_runtime.h>
#include <math.h>

#define Bx 256
#define Sx 196
#define Rx 2048
#define Ax 512
#define NSPLIT 16
#define KCHUNK (Rx / NSPLIT)  // 128

// Scratch (allocation-free rule: __device__ globals)
__device__ float g_part[NSPLIT * Bx * Ax];   // 8 MB split-K partials
__device__ float g_weight[Bx * Sx];          // 200 KB

// Fast accurate tanh: 2x MUFU (EX2 via __expf, RCP) + few FMA, ~1e-7 rel err.
__device__ __forceinline__ float fast_tanh(float x) {
    float ax = fabsf(x);
    float t = __expf(-2.0f * ax);          // in (0,1], no overflow
    float r = (1.0f - t) * __frcp_rn(1.0f + t);
    return copysignf(r, x);
}

// ---------------------------------------------------------------------------
// K1: att_h partials = h[B,R] @ W_h[R,A], split-K over z.
// BM=128 BN=64 BK=16, 256 threads, 8x4 per-thread tile.
// grid (8, 2, 16) = 256 blocks -> 2 CTAs resident per SM, one wave.
// ---------------------------------------------------------------------------
__global__ __launch_bounds__(256)
void k_gemm(const float* __restrict__ h, const float* __restrict__ Wh) {
    const int BM = 128, BN = 64, BK = 16;
    __shared__ float As[BK][BM + 4];  // transposed A tile, padded
    __shared__ float Bs[BK][BN];

    int tid = threadIdx.x;
    int tx = tid & 15;       // 0..15 -> N (4 cols each)
    int ty = tid >> 4;       // 0..15 -> M (8 rows each)
    int bm = blockIdx.y * BM;
    int bn = blockIdx.x * BN;
    int kc0 = blockIdx.z * KCHUNK;

    float acc[8][4];
#pragma unroll
    for (int i = 0; i < 8; i++)
#pragma unroll
        for (int j = 0; j < 4; j++) acc[i][j] = 0.f;

    for (int kc = kc0; kc < kc0 + KCHUNK; kc += BK) {
        // Load A tile (128 x 16): 2048 floats, 8 per thread, store transposed
#pragma unroll
        for (int j = 0; j < 8; j++) {
            int lin = tid + 256 * j;
            int row = lin >> 4, col = lin & 15;
            As[col][row] = h[(size_t)(bm + row) * Rx + kc + col];
        }
        // Load B tile (16 x 64): 1024 floats, 4 per thread, coalesced
#pragma unroll
        for (int j = 0; j < 4; j++) {
            int lin = tid + 256 * j;
            int row = lin >> 6, col = lin & 63;
            Bs[row][col] = Wh[(size_t)(kc + row) * Ax + bn + col];
        }
        __syncthreads();

#pragma unroll
        for (int kk = 0; kk < BK; kk++) {
            float4 a0 = *reinterpret_cast<const float4*>(&As[kk][ty * 8]);
            float4 a1 = *reinterpret_cast<const float4*>(&As[kk][ty * 8 + 4]);
            float4 b4 = *reinterpret_cast<const float4*>(&Bs[kk][tx * 4]);
            float av[8] = {a0.x, a0.y, a0.z, a0.w, a1.x, a1.y, a1.z, a1.w};
            float bv[4] = {b4.x, b4.y, b4.z, b4.w};
#pragma unroll
            for (int i = 0; i < 8; i++)
#pragma unroll
                for (int j = 0; j < 4; j++)
                    acc[i][j] += av[i] * bv[j];
        }
        __syncthreads();
    }

    float* out = g_part + (size_t)blockIdx.z * Bx * Ax;
#pragma unroll
    for (int i = 0; i < 8; i++) {
        int m = bm + ty * 8 + i;
        float4 v = make_float4(acc[i][0], acc[i][1], acc[i][2], acc[i][3]);
        *reinterpret_cast<float4*>(&out[(size_t)m * Ax + bn + tx * 4]) = v;
    }
}

// ---------------------------------------------------------------------------
// K2: scores[b,s] = sum_a tanh(p_att[b,s,a] + att_h[b,a]) * W_a[a] + b_a
//     att_h reduced inline from split-K partials (+ bias).
//     Then softmax over s. One block per b, 256 threads (8 warps).
// ---------------------------------------------------------------------------
__global__ void k_scores(const float* __restrict__ p_att,
                         const unsigned char* __restrict__ mask,
                         const float* __restrict__ W_a,
                         const float* __restrict__ b_a,
                         const float* __restrict__ b_h) {
    int b = blockIdx.x;
    __shared__ float sh_ah[Ax];
    __shared__ float sh_wa[Ax];
    __shared__ float sh_sc[Sx];
    __shared__ float red[40];

    int tid = threadIdx.x;
    // reduce split-K partials + bias into shared att_h (2 elements/thread)
#pragma unroll
    for (int e = 0; e < 2; e++) {
        int a = tid + 256 * e;
        float v = b_h[a];
#pragma unroll
        for (int z = 0; z < NSPLIT; z++)
            v += g_part[(size_t)z * Bx * Ax + (size_t)b * Ax + a];
        sh_ah[a] = v;
        sh_wa[a] = W_a[a];
    }
    __syncthreads();

    int warp = tid >> 5, lane = tid & 31;
    float ba = b_a[0];

    for (int s = warp; s < Sx; s += 8) {
        const float4* p = reinterpret_cast<const float4*>(p_att + ((size_t)b * Sx + s) * Ax);
        float acc = 0.f;
#pragma unroll
        for (int i = 0; i < 4; i++) {
            float4 v  = __ldcs(&p[lane + 32 * i]);
            float4 ah = reinterpret_cast<const float4*>(sh_ah)[lane + 32 * i];
            float4 wa = reinterpret_cast<const float4*>(sh_wa)[lane + 32 * i];
            acc += fast_tanh(v.x + ah.x) * wa.x;
            acc += fast_tanh(v.y + ah.y) * wa.y;
            acc += fast_tanh(v.z + ah.z) * wa.z;
            acc += fast_tanh(v.w + ah.w) * wa.w;
        }
#pragma unroll
        for (int o = 16; o > 0; o >>= 1) acc += __shfl_xor_sync(0xffffffffu, acc, o);
        if (lane == 0) {
            float sc = acc + ba;
            if (mask[(size_t)b * Sx + s]) sc = -100000000.0f;
            sh_sc[s] = sc;
        }
    }
    __syncthreads();

    // softmax over S=196 using 256 threads
    float v = (tid < Sx) ? sh_sc[tid] : -INFINITY;
    float m = v;
#pragma unroll
    for (int o = 16; o > 0; o >>= 1) m = fmaxf(m, __shfl_xor_sync(0xffffffffu, m, o));
    if (lane == 0) red[warp] = m;
    __syncthreads();
    if (tid == 0) {
        float mm = red[0];
#pragma unroll
        for (int i = 1; i < 8; i++) mm = fmaxf(mm, red[i]);
        red[32] = mm;
    }
    __syncthreads();
    float smax = red[32];

    float e = (tid < Sx) ? __expf(v - smax) : 0.f;
    float ssum = e;
#pragma unroll
    for (int o = 16; o > 0; o >>= 1) ssum += __shfl_xor_sync(0xffffffffu, ssum, o);
    if (lane == 0) red[warp] = ssum;
    __syncthreads();
    if (tid == 0) {
        float t = 0.f;
#pragma unroll
        for (int i = 0; i < 8; i++) t += red[i];
        red[33] = t;
    }
    __syncthreads();
    float inv = 1.0f / red[33];
    if (tid < Sx) g_weight[(size_t)b * Sx + tid] = e * inv;
}

// ---------------------------------------------------------------------------
// K3: att_res[b,r] = sum_s weight[b,s] * att_feats[b,s,r]
//     grid (4, B), 128 threads, each thread one float4 column slice.
//     HBM-streaming: 411 MB read; __ldcs (evict-first) + unroll 8 for MLP.
// ---------------------------------------------------------------------------
__global__ void k_wsum(const float* __restrict__ att_feats, float* __restrict__ out) {
    int b = blockIdx.y;
    int tid = threadIdx.x;  // 0..127
    __shared__ float sw[Sx];
    for (int i = tid; i < Sx; i += 128) sw[i] = g_weight[(size_t)b * Sx + i];
    __syncthreads();

    const float4* base = reinterpret_cast<const float4*>(att_feats + (size_t)b * Sx * Rx)
                         + blockIdx.x * 128 + tid;
    float4 acc = make_float4(0.f, 0.f, 0.f, 0.f);
#pragma unroll 2
    for (int s0 = 0; s0 < 192; s0 += 8) {
        float4 v[8];
#pragma unroll
        for (int u = 0; u < 8; u++)
            v[u] = __ldcs(&base[(size_t)(s0 + u) * (Rx / 4)]);
#pragma unroll
        for (int u = 0; u < 8; u++) {
            float w = sw[s0 + u];
            acc.x += w * v[u].x;
            acc.y += w * v[u].y;
            acc.z += w * v[u].z;
            acc.w += w * v[u].w;
        }
    }
#pragma unroll
    for (int s = 192; s < Sx; s++) {
        float w = sw[s];
        float4 v = __ldcs(&base[(size_t)s * (Rx / 4)]);
        acc.x += w * v.x;
        acc.y += w * v.y;
        acc.z += w * v.z;
        acc.w += w * v.w;
    }
    reinterpret_cast<float4*>(out + (size_t)b * Rx)[blockIdx.x * 128 + tid] = acc;
}

// ---------------------------------------------------------------------------
extern "C" void kernel_launch(void* const* d_in, const int* in_sizes, int n_in,
                              void* d_out, int out_size) {
    const float*         h         = (const float*)d_in[0];
    const float*         att_feats = (const float*)d_in[1];
    const float*         p_att     = (const float*)d_in[2];
    const unsigned char* mask      = (const unsigned char*)d_in[3];
    const float*         W_h       = (const float*)d_in[4];
    const float*         b_h       = (const float*)d_in[5];
    const float*         W_a       = (const float*)d_in[6];
    const float*         b_a       = (const float*)d_in[7];
    float*               out       = (float*)d_out;

    k_gemm<<<dim3(Ax / 64, Bx / 128, NSPLIT), 256>>>(h, W_h);
    k_scores<<<Bx, 256>>>(p_att, mask, W_a, b_a, b_h);
    k_wsum<<<dim3(4, Bx), 128>>>(att_feats, out);
}

// round 4
// speedup vs baseline: 1.2182x; 1.2182x over previous
#include <cuda_runtime.h>
#include <math.h>

#define Bx 256
#define Sx 196
#define Rx 2048
#define Ax 512
#define NSPLIT 16
#define KCHUNK (Rx / NSPLIT)  // 128

// Scratch (allocation-free rule: __device__ globals)
__device__ float g_part[NSPLIT * Bx * Ax];   // 8 MB split-K partials
__device__ float g_weight[Bx * Sx];          // 200 KB

// Fast accurate tanh: MUFU.EX2 (+scale) + MUFU.RCP + FMA. ~1e-7 rel err.
// tanh(x) = sign(x) * (1 - 2/(exp(2|x|)+1));  exp overflow -> rcp(inf)=0 -> 1. OK.
__device__ __forceinline__ float fast_tanh(float x) {
    float ax = fabsf(x);
    float e = __expf(2.0f * ax);     // MUFU.EX2 path (fast)
    float r;
    asm("rcp.approx.f32 %0, %1;" : "=f"(r) : "f"(e + 1.0f));  // MUFU.RCP
    r = fmaf(-2.0f, r, 1.0f);
    return copysignf(r, x);
}

// ---------------------------------------------------------------------------
// K1: att_h partials = h[B,R] @ W_h[R,A], split-K over z.
// BM=128 BN=64 BK=16, 256 threads, 8x4 per-thread tile.
// grid (8, 2, 16) = 256 blocks -> 2 CTAs resident per SM.
// ---------------------------------------------------------------------------
__global__ __launch_bounds__(256)
void k_gemm(const float* __restrict__ h, const float* __restrict__ Wh) {
    const int BM = 128, BN = 64, BK = 16;
    __shared__ float As[BK][BM + 4];  // transposed A tile, padded
    __shared__ float Bs[BK][BN];

    int tid = threadIdx.x;
    int tx = tid & 15;       // 0..15 -> N (4 cols each)
    int ty = tid >> 4;       // 0..15 -> M (8 rows each)
    int bm = blockIdx.y * BM;
    int bn = blockIdx.x * BN;
    int kc0 = blockIdx.z * KCHUNK;

    float acc[8][4];
#pragma unroll
    for (int i = 0; i < 8; i++)
#pragma unroll
        for (int j = 0; j < 4; j++) acc[i][j] = 0.f;

    for (int kc = kc0; kc < kc0 + KCHUNK; kc += BK) {
        // Load A tile (128 x 16): 2048 floats, 8 per thread, store transposed
#pragma unroll
        for (int j = 0; j < 8; j++) {
            int lin = tid + 256 * j;
            int row = lin >> 4, col = lin & 15;
            As[col][row] = h[(size_t)(bm + row) * Rx + kc + col];
        }
        // Load B tile (16 x 64): 1024 floats, 4 per thread, coalesced
#pragma unroll
        for (int j = 0; j < 4; j++) {
            int lin = tid + 256 * j;
            int row = lin >> 6, col = lin & 63;
            Bs[row][col] = Wh[(size_t)(kc + row) * Ax + bn + col];
        }
        __syncthreads();

#pragma unroll
        for (int kk = 0; kk < BK; kk++) {
            float4 a0 = *reinterpret_cast<const float4*>(&As[kk][ty * 8]);
            float4 a1 = *reinterpret_cast<const float4*>(&As[kk][ty * 8 + 4]);
            float4 b4 = *reinterpret_cast<const float4*>(&Bs[kk][tx * 4]);
            float av[8] = {a0.x, a0.y, a0.z, a0.w, a1.x, a1.y, a1.z, a1.w};
            float bv[4] = {b4.x, b4.y, b4.z, b4.w};
#pragma unroll
            for (int i = 0; i < 8; i++)
#pragma unroll
                for (int j = 0; j < 4; j++)
                    acc[i][j] += av[i] * bv[j];
        }
        __syncthreads();
    }

    float* out = g_part + (size_t)blockIdx.z * Bx * Ax;
#pragma unroll
    for (int i = 0; i < 8; i++) {
        int m = bm + ty * 8 + i;
        float4 v = make_float4(acc[i][0], acc[i][1], acc[i][2], acc[i][3]);
        *reinterpret_cast<float4*>(&out[(size_t)m * Ax + bn + tx * 4]) = v;
    }
}

// ---------------------------------------------------------------------------
// K2: scores[b,s] = sum_a tanh(p_att[b,s,a] + att_h[b,a]) * W_a[a] + b_a
//     att_h reduced inline from split-K partials (+ bias).
//     Then softmax over s. One block per b, 256 threads (8 warps).
// ---------------------------------------------------------------------------
__global__ void k_scores(const float* __restrict__ p_att,
                         const unsigned char* __restrict__ mask,
                         const float* __restrict__ W_a,
                         const float* __restrict__ b_a,
                         const float* __restrict__ b_h) {
    int b = blockIdx.x;
    __shared__ float sh_ah[Ax];
    __shared__ float sh_wa[Ax];
    __shared__ float sh_sc[Sx];
    __shared__ float red[40];

    int tid = threadIdx.x;
    // reduce split-K partials + bias into shared att_h (2 elements/thread)
#pragma unroll
    for (int e = 0; e < 2; e++) {
        int a = tid + 256 * e;
        float v = b_h[a];
#pragma unroll
        for (int z = 0; z < NSPLIT; z++)
            v += g_part[(size_t)z * Bx * Ax + (size_t)b * Ax + a];
        sh_ah[a] = v;
        sh_wa[a] = W_a[a];
    }
    __syncthreads();

    int warp = tid >> 5, lane = tid & 31;
    float ba = b_a[0];

    for (int s = warp; s < Sx; s += 8) {
        const float4* p = reinterpret_cast<const float4*>(p_att + ((size_t)b * Sx + s) * Ax);
        float acc = 0.f;
#pragma unroll
        for (int i = 0; i < 4; i++) {
            float4 v  = __ldcs(&p[lane + 32 * i]);
            float4 ah = reinterpret_cast<const float4*>(sh_ah)[lane + 32 * i];
            float4 wa = reinterpret_cast<const float4*>(sh_wa)[lane + 32 * i];
            acc += fast_tanh(v.x + ah.x) * wa.x;
            acc += fast_tanh(v.y + ah.y) * wa.y;
            acc += fast_tanh(v.z + ah.z) * wa.z;
            acc += fast_tanh(v.w + ah.w) * wa.w;
        }
#pragma unroll
        for (int o = 16; o > 0; o >>= 1) acc += __shfl_xor_sync(0xffffffffu, acc, o);
        if (lane == 0) {
            float sc = acc + ba;
            if (mask[(size_t)b * Sx + s]) sc = -100000000.0f;
            sh_sc[s] = sc;
        }
    }
    __syncthreads();

    // softmax over S=196 using 256 threads
    float v = (tid < Sx) ? sh_sc[tid] : -INFINITY;
    float m = v;
#pragma unroll
    for (int o = 16; o > 0; o >>= 1) m = fmaxf(m, __shfl_xor_sync(0xffffffffu, m, o));
    if (lane == 0) red[warp] = m;
    __syncthreads();
    if (tid == 0) {
        float mm = red[0];
#pragma unroll
        for (int i = 1; i < 8; i++) mm = fmaxf(mm, red[i]);
        red[32] = mm;
    }
    __syncthreads();
    float smax = red[32];

    float e = (tid < Sx) ? __expf(v - smax) : 0.f;
    float ssum = e;
#pragma unroll
    for (int o = 16; o > 0; o >>= 1) ssum += __shfl_xor_sync(0xffffffffu, ssum, o);
    if (lane == 0) red[warp] = ssum;
    __syncthreads();
    if (tid == 0) {
        float t = 0.f;
#pragma unroll
        for (int i = 0; i < 8; i++) t += red[i];
        red[33] = t;
    }
    __syncthreads();
    float inv = 1.0f / red[33];
    if (tid < Sx) g_weight[(size_t)b * Sx + tid] = e * inv;
}

// ---------------------------------------------------------------------------
// K3: att_res[b,r] = sum_s weight[b,s] * att_feats[b,s,r]
//     grid (4, B), 128 threads, each thread one float4 column slice.
//     HBM-streaming: 411 MB read; __ldcs (evict-first) + unroll 8 for MLP.
// ---------------------------------------------------------------------------
__global__ void k_wsum(const float* __restrict__ att_feats, float* __restrict__ out) {
    int b = blockIdx.y;
    int tid = threadIdx.x;  // 0..127
    __shared__ float sw[Sx];
    for (int i = tid; i < Sx; i += 128) sw[i] = g_weight[(size_t)b * Sx + i];
    __syncthreads();

    const float4* base = reinterpret_cast<const float4*>(att_feats + (size_t)b * Sx * Rx)
                         + blockIdx.x * 128 + tid;
    float4 acc = make_float4(0.f, 0.f, 0.f, 0.f);
#pragma unroll 2
    for (int s0 = 0; s0 < 192; s0 += 8) {
        float4 v[8];
#pragma unroll
        for (int u = 0; u < 8; u++)
            v[u] = __ldcs(&base[(size_t)(s0 + u) * (Rx / 4)]);
#pragma unroll
        for (int u = 0; u < 8; u++) {
            float w = sw[s0 + u];
            acc.x += w * v[u].x;
            acc.y += w * v[u].y;
            acc.z += w * v[u].z;
            acc.w += w * v[u].w;
        }
    }
#pragma unroll
    for (int s = 192; s < Sx; s++) {
        float w = sw[s];
        float4 v = __ldcs(&base[(size_t)s * (Rx / 4)]);
        acc.x += w * v.x;
        acc.y += w * v.y;
        acc.z += w * v.z;
        acc.w += w * v.w;
    }
    reinterpret_cast<float4*>(out + (size_t)b * Rx)[blockIdx.x * 128 + tid] = acc;
}

// ---------------------------------------------------------------------------
extern "C" void kernel_launch(void* const* d_in, const int* in_sizes, int n_in,
                              void* d_out, int out_size) {
    const float*         h         = (const float*)d_in[0];
    const float*         att_feats = (const float*)d_in[1];
    const float*         p_att     = (const float*)d_in[2];
    const unsigned char* mask      = (const unsigned char*)d_in[3];
    const float*         W_h       = (const float*)d_in[4];
    const float*         b_h       = (const float*)d_in[5];
    const float*         W_a       = (const float*)d_in[6];
    const float*         b_a       = (const float*)d_in[7];
    float*               out       = (float*)d_out;

    k_gemm<<<dim3(Ax / 64, Bx / 128, NSPLIT), 256>>>(h, W_h);
    k_scores<<<Bx, 256>>>(p_att, mask, W_a, b_a, b_h);
    k_wsum<<<dim3(4, Bx), 128>>>(att_feats, out);
}

// round 5
// speedup vs baseline: 1.4228x; 1.1679x over previous
#include <cuda_runtime.h>
#include <math.h>

#define Bx 256
#define Sx 196
#define Rx 2048
#define Ax 512
#define NSPLIT 16
#define KCHUNK (Rx / NSPLIT)  // 128
#define SCHUNK 49             // rows per score block (4 blocks per batch)

// Scratch (allocation-free rule: __device__ globals)
__device__ float g_part[NSPLIT * Bx * Ax];   // 8 MB split-K partials
__device__ float g_att_h[Bx * Ax];           // 512 KB
__device__ float g_scores[Bx * Sx];          // 200 KB raw scores
__device__ float g_weight[Bx * Sx];          // 200 KB softmax weights

// Fast tanh: MUFU.EX2 + MUFU.RCP + FMA. ~1e-7 rel err.
// tanh(x) = sign(x) * (1 - 2/(exp(2|x|)+1)); exp overflow -> rcp=0 -> 1. OK.
__device__ __forceinline__ float fast_tanh(float x) {
    float ax = fabsf(x);
    float e = __expf(2.0f * ax);
    float r;
    asm("rcp.approx.f32 %0, %1;" : "=f"(r) : "f"(e + 1.0f));
    r = fmaf(-2.0f, r, 1.0f);
    return copysignf(r, x);
}

// ---------------------------------------------------------------------------
// K1: att_h partials = h[B,R] @ W_h[R,A], split-K over z.
// BM=128 BN=64 BK=16, 256 threads, 8x4 per-thread tile. grid (8,2,16)=256.
// ---------------------------------------------------------------------------
__global__ __launch_bounds__(256)
void k_gemm(const float* __restrict__ h, const float* __restrict__ Wh) {
    const int BM = 128, BN = 64, BK = 16;
    __shared__ float As[BK][BM + 4];
    __shared__ float Bs[BK][BN];

    int tid = threadIdx.x;
    int tx = tid & 15;
    int ty = tid >> 4;
    int bm = blockIdx.y * BM;
    int bn = blockIdx.x * BN;
    int kc0 = blockIdx.z * KCHUNK;

    float acc[8][4];
#pragma unroll
    for (int i = 0; i < 8; i++)
#pragma unroll
        for (int j = 0; j < 4; j++) acc[i][j] = 0.f;

    for (int kc = kc0; kc < kc0 + KCHUNK; kc += BK) {
#pragma unroll
        for (int j = 0; j < 8; j++) {
            int lin = tid + 256 * j;
            int row = lin >> 4, col = lin & 15;
            As[col][row] = h[(size_t)(bm + row) * Rx + kc + col];
        }
#pragma unroll
        for (int j = 0; j < 4; j++) {
            int lin = tid + 256 * j;
            int row = lin >> 6, col = lin & 63;
            Bs[row][col] = Wh[(size_t)(kc + row) * Ax + bn + col];
        }
        __syncthreads();

#pragma unroll
        for (int kk = 0; kk < BK; kk++) {
            float4 a0 = *reinterpret_cast<const float4*>(&As[kk][ty * 8]);
            float4 a1 = *reinterpret_cast<const float4*>(&As[kk][ty * 8 + 4]);
            float4 b4 = *reinterpret_cast<const float4*>(&Bs[kk][tx * 4]);
            float av[8] = {a0.x, a0.y, a0.z, a0.w, a1.x, a1.y, a1.z, a1.w};
            float bv[4] = {b4.x, b4.y, b4.z, b4.w};
#pragma unroll
            for (int i = 0; i < 8; i++)
#pragma unroll
                for (int j = 0; j < 4; j++)
                    acc[i][j] += av[i] * bv[j];
        }
        __syncthreads();
    }

    float* out = g_part + (size_t)blockIdx.z * Bx * Ax;
#pragma unroll
    for (int i = 0; i < 8; i++) {
        int m = bm + ty * 8 + i;
        float4 v = make_float4(acc[i][0], acc[i][1], acc[i][2], acc[i][3]);
        *reinterpret_cast<float4*>(&out[(size_t)m * Ax + bn + tx * 4]) = v;
    }
}

// ---------------------------------------------------------------------------
// K1b: att_h = b_h + sum_z partials
// ---------------------------------------------------------------------------
__global__ void k_reduce(const float* __restrict__ b_h) {
    int idx = blockIdx.x * 256 + threadIdx.x;
    float acc = b_h[idx & (Ax - 1)];
#pragma unroll
    for (int z = 0; z < NSPLIT; z++) acc += g_part[(size_t)z * Bx * Ax + idx];
    g_att_h[idx] = acc;
}

// ---------------------------------------------------------------------------
// K2a: raw scores. grid (4, B): block q handles 49 rows of batch b.
// 256 threads = 8 warps; one warp per row, 16 elems/lane.
// High grid count -> enough warps/SM to overlap MUFU + issue + HBM stream.
// ---------------------------------------------------------------------------
__global__ __launch_bounds__(256)
void k_scores_raw(const float* __restrict__ p_att,
                  const float* __restrict__ W_a,
                  const float* __restrict__ b_a) {
    int b = blockIdx.y;
    int q = blockIdx.x;
    __shared__ float sh_ah[Ax];
    __shared__ float sh_wa[Ax];

    int tid = threadIdx.x;
#pragma unroll
    for (int e = 0; e < 2; e++) {
        int a = tid + 256 * e;
        sh_ah[a] = g_att_h[(size_t)b * Ax + a];
        sh_wa[a] = W_a[a];
    }
    __syncthreads();

    int warp = tid >> 5, lane = tid & 31;
    float ba = b_a[0];
    int s_end = (q + 1) * SCHUNK;
    if (s_end > Sx) s_end = Sx;

    for (int s = q * SCHUNK + warp; s < s_end; s += 8) {
        const float4* p = reinterpret_cast<const float4*>(p_att + ((size_t)b * Sx + s) * Ax);
        float acc = 0.f;
#pragma unroll
        for (int i = 0; i < 4; i++) {
            float4 v  = __ldcs(&p[lane + 32 * i]);
            float4 ah = reinterpret_cast<const float4*>(sh_ah)[lane + 32 * i];
            float4 wa = reinterpret_cast<const float4*>(sh_wa)[lane + 32 * i];
            acc += fast_tanh(v.x + ah.x) * wa.x;
            acc += fast_tanh(v.y + ah.y) * wa.y;
            acc += fast_tanh(v.z + ah.z) * wa.z;
            acc += fast_tanh(v.w + ah.w) * wa.w;
        }
#pragma unroll
        for (int o = 16; o > 0; o >>= 1) acc += __shfl_xor_sync(0xffffffffu, acc, o);
        if (lane == 0) g_scores[(size_t)b * Sx + s] = acc + ba;
    }
}

// ---------------------------------------------------------------------------
// K2b: mask + softmax over s. One block per b, 256 threads.
// ---------------------------------------------------------------------------
__global__ void k_softmax(const unsigned char* __restrict__ mask) {
    int b = blockIdx.x;
    __shared__ float red[40];
    int tid = threadIdx.x;
    int warp = tid >> 5, lane = tid & 31;

    float v = -INFINITY;
    if (tid < Sx) {
        v = g_scores[(size_t)b * Sx + tid];
        if (mask[(size_t)b * Sx + tid]) v = -100000000.0f;
    }
    float m = v;
#pragma unroll
    for (int o = 16; o > 0; o >>= 1) m = fmaxf(m, __shfl_xor_sync(0xffffffffu, m, o));
    if (lane == 0) red[warp] = m;
    __syncthreads();
    if (tid == 0) {
        float mm = red[0];
#pragma unroll
        for (int i = 1; i < 8; i++) mm = fmaxf(mm, red[i]);
        red[32] = mm;
    }
    __syncthreads();
    float smax = red[32];

    float e = (tid < Sx) ? __expf(v - smax) : 0.f;
    float ssum = e;
#pragma unroll
    for (int o = 16; o > 0; o >>= 1) ssum += __shfl_xor_sync(0xffffffffu, ssum, o);
    if (lane == 0) red[warp] = ssum;
    __syncthreads();
    if (tid == 0) {
        float t = 0.f;
#pragma unroll
        for (int i = 0; i < 8; i++) t += red[i];
        red[33] = t;
    }
    __syncthreads();
    float inv = 1.0f / red[33];
    if (tid < Sx) g_weight[(size_t)b * Sx + tid] = e * inv;
}

// ---------------------------------------------------------------------------
// K3: att_res[b,r] = sum_s weight[b,s] * att_feats[b,s,r]
// grid (4, B), 128 threads; HBM streaming with __ldcs + unroll 8.
// ---------------------------------------------------------------------------
__global__ void k_wsum(const float* __restrict__ att_feats, float* __restrict__ out) {
    int b = blockIdx.y;
    int tid = threadIdx.x;
    __shared__ float sw[Sx];
    for (int i = tid; i < Sx; i += 128) sw[i] = g_weight[(size_t)b * Sx + i];
    __syncthreads();

    const float4* base = reinterpret_cast<const float4*>(att_feats + (size_t)b * Sx * Rx)
                         + blockIdx.x * 128 + tid;
    float4 acc = make_float4(0.f, 0.f, 0.f, 0.f);
#pragma unroll 2
    for (int s0 = 0; s0 < 192; s0 += 8) {
        float4 v[8];
#pragma unroll
        for (int u = 0; u < 8; u++)
            v[u] = __ldcs(&base[(size_t)(s0 + u) * (Rx / 4)]);
#pragma unroll
        for (int u = 0; u < 8; u++) {
            float w = sw[s0 + u];
            acc.x += w * v[u].x;
            acc.y += w * v[u].y;
            acc.z += w * v[u].z;
            acc.w += w * v[u].w;
        }
    }
#pragma unroll
    for (int s = 192; s < Sx; s++) {
        float w = sw[s];
        float4 v = __ldcs(&base[(size_t)s * (Rx / 4)]);
        acc.x += w * v.x;
        acc.y += w * v.y;
        acc.z += w * v.z;
        acc.w += w * v.w;
    }
    reinterpret_cast<float4*>(out + (size_t)b * Rx)[blockIdx.x * 128 + tid] = acc;
}

// ---------------------------------------------------------------------------
extern "C" void kernel_launch(void* const* d_in, const int* in_sizes, int n_in,
                              void* d_out, int out_size) {
    const float*         h         = (const float*)d_in[0];
    const float*         att_feats = (const float*)d_in[1];
    const float*         p_att     = (const float*)d_in[2];
    const unsigned char* mask      = (const unsigned char*)d_in[3];
    const float*         W_h       = (const float*)d_in[4];
    const float*         b_h       = (const float*)d_in[5];
    const float*         W_a       = (const float*)d_in[6];
    const float*         b_a       = (const float*)d_in[7];
    float*               out       = (float*)d_out;

    k_gemm<<<dim3(Ax / 64, Bx / 128, NSPLIT), 256>>>(h, W_h);
    k_reduce<<<(Bx * Ax) / 256, 256>>>(b_h);
    k_scores_raw<<<dim3(4, Bx), 256>>>(p_att, W_a, b_a);
    k_softmax<<<Bx, 256>>>(mask);
    k_wsum<<<dim3(4, Bx), 128>>>(att_feats, out);
}

// round 6
// speedup vs baseline: 1.5024x; 1.0560x over previous
#include <cuda_runtime.h>
#include <math.h>

#define Bx 256
#define Sx 196
#define Rx 2048
#define Ax 512
#define NSPLIT 16
#define KCHUNK (Rx / NSPLIT)  // 128
#define SCHUNK 49             // rows per score block (4 blocks per batch)

// Scratch (allocation-free rule: __device__ globals)
__device__ float g_part[NSPLIT * Bx * Ax];   // 8 MB split-K partials
__device__ float g_scores[Bx * Sx];          // 200 KB raw scores

// Fast tanh: MUFU.EX2 + MUFU.RCP + FMA. ~1e-7 rel err.
__device__ __forceinline__ float fast_tanh(float x) {
    float ax = fabsf(x);
    float e = __expf(2.0f * ax);
    float r;
    asm("rcp.approx.f32 %0, %1;" : "=f"(r) : "f"(e + 1.0f));
    r = fmaf(-2.0f, r, 1.0f);
    return copysignf(r, x);
}

// ---------------------------------------------------------------------------
// K1: att_h partials = h[B,R] @ W_h[R,A], split-K over z.
// BM=128 BN=64 BK=16, 256 threads, 8x4 tile, double-buffered smem,
// ONE barrier per K-step (store -> sync -> prefetch -> compute).
// ---------------------------------------------------------------------------
__global__ __launch_bounds__(256)
void k_gemm(const float* __restrict__ h, const float* __restrict__ Wh) {
    const int BM = 128, BN = 64, BK = 16;
    __shared__ float As[2][BK][BM + 4];
    __shared__ float Bs[2][BK][BN];

    int tid = threadIdx.x;
    int tx = tid & 15;
    int ty = tid >> 4;
    int bm = blockIdx.y * BM;
    int bn = blockIdx.x * BN;
    int kc0 = blockIdx.z * KCHUNK;

    float acc[8][4];
#pragma unroll
    for (int i = 0; i < 8; i++)
#pragma unroll
        for (int j = 0; j < 4; j++) acc[i][j] = 0.f;

    float pa[8], pb[4];
    // preload tile 0 into registers
#pragma unroll
    for (int j = 0; j < 8; j++) {
        int lin = tid + 256 * j;
        pa[j] = h[(size_t)(bm + (lin >> 4)) * Rx + kc0 + (lin & 15)];
    }
#pragma unroll
    for (int j = 0; j < 4; j++) {
        int lin = tid + 256 * j;
        pb[j] = Wh[(size_t)(kc0 + (lin >> 6)) * Ax + bn + (lin & 63)];
    }

    const int NT = KCHUNK / BK;  // 8
#pragma unroll
    for (int t = 0; t < NT; t++) {
        int cur = t & 1;
        // store prefetched tile to current buffer
#pragma unroll
        for (int j = 0; j < 8; j++) {
            int lin = tid + 256 * j;
            As[cur][lin & 15][lin >> 4] = pa[j];
        }
#pragma unroll
        for (int j = 0; j < 4; j++) {
            int lin = tid + 256 * j;
            Bs[cur][lin >> 6][lin & 63] = pb[j];
        }
        __syncthreads();

        // prefetch next tile (global loads overlap compute below)
        if (t < NT - 1) {
            int kc = kc0 + (t + 1) * BK;
#pragma unroll
            for (int j = 0; j < 8; j++) {
                int lin = tid + 256 * j;
                pa[j] = h[(size_t)(bm + (lin >> 4)) * Rx + kc + (lin & 15)];
            }
#pragma unroll
            for (int j = 0; j < 4; j++) {
                int lin = tid + 256 * j;
                pb[j] = Wh[(size_t)(kc + (lin >> 6)) * Ax + bn + (lin & 63)];
            }
        }

#pragma unroll
        for (int kk = 0; kk < BK; kk++) {
            float4 a0 = *reinterpret_cast<const float4*>(&As[cur][kk][ty * 8]);
            float4 a1 = *reinterpret_cast<const float4*>(&As[cur][kk][ty * 8 + 4]);
            float4 b4 = *reinterpret_cast<const float4*>(&Bs[cur][kk][tx * 4]);
            float av[8] = {a0.x, a0.y, a0.z, a0.w, a1.x, a1.y, a1.z, a1.w};
            float bv[4] = {b4.x, b4.y, b4.z, b4.w};
#pragma unroll
            for (int i = 0; i < 8; i++)
#pragma unroll
                for (int j = 0; j < 4; j++)
                    acc[i][j] += av[i] * bv[j];
        }
        // no trailing sync needed: next store targets the other buffer, and
        // the barrier above (iter t+1) orders it against all compute(t).
    }

    float* out = g_part + (size_t)blockIdx.z * Bx * Ax;
#pragma unroll
    for (int i = 0; i < 8; i++) {
        int m = bm + ty * 8 + i;
        float4 v = make_float4(acc[i][0], acc[i][1], acc[i][2], acc[i][3]);
        *reinterpret_cast<float4*>(&out[(size_t)m * Ax + bn + tx * 4]) = v;
    }
}

// ---------------------------------------------------------------------------
// K2: raw scores. grid (4, B): block q handles 49 rows of batch b.
// att_h reduced inline from split-K partials (+ b_h) — L2-resident reads.
// ---------------------------------------------------------------------------
__global__ __launch_bounds__(256)
void k_scores_raw(const float* __restrict__ p_att,
                  const float* __restrict__ W_a,
                  const float* __restrict__ b_a,
                  const float* __restrict__ b_h) {
    int b = blockIdx.y;
    int q = blockIdx.x;
    __shared__ float sh_ah[Ax];
    __shared__ float sh_wa[Ax];

    int tid = threadIdx.x;
#pragma unroll
    for (int e = 0; e < 2; e++) {
        int a = tid + 256 * e;
        float v = b_h[a];
#pragma unroll
        for (int z = 0; z < NSPLIT; z++)
            v += g_part[(size_t)z * Bx * Ax + (size_t)b * Ax + a];
        sh_ah[a] = v;
        sh_wa[a] = W_a[a];
    }
    __syncthreads();

    int warp = tid >> 5, lane = tid & 31;
    float ba = b_a[0];
    int s_end = (q + 1) * SCHUNK;
    if (s_end > Sx) s_end = Sx;

    for (int s = q * SCHUNK + warp; s < s_end; s += 8) {
        const float4* p = reinterpret_cast<const float4*>(p_att + ((size_t)b * Sx + s) * Ax);
        float acc = 0.f;
#pragma unroll
        for (int i = 0; i < 4; i++) {
            float4 v  = __ldcs(&p[lane + 32 * i]);
            float4 ah = reinterpret_cast<const float4*>(sh_ah)[lane + 32 * i];
            float4 wa = reinterpret_cast<const float4*>(sh_wa)[lane + 32 * i];
            acc += fast_tanh(v.x + ah.x) * wa.x;
            acc += fast_tanh(v.y + ah.y) * wa.y;
            acc += fast_tanh(v.z + ah.z) * wa.z;
            acc += fast_tanh(v.w + ah.w) * wa.w;
        }
#pragma unroll
        for (int o = 16; o > 0; o >>= 1) acc += __shfl_xor_sync(0xffffffffu, acc, o);
        if (lane == 0) g_scores[(size_t)b * Sx + s] = acc + ba;
    }
}

// ---------------------------------------------------------------------------
// K3: softmax (redundant per block, L2-resident) + weighted sum.
// grid (4, B), 128 threads. HBM streaming with __ldcs + unroll 8.
// ---------------------------------------------------------------------------
__global__ __launch_bounds__(128)
void k_wsum(const float* __restrict__ att_feats,
            const unsigned char* __restrict__ mask,
            float* __restrict__ out) {
    int b = blockIdx.y;
    int tid = threadIdx.x;  // 0..127
    __shared__ float sw[Sx];
    __shared__ float red[8];
    int warp = tid >> 5, lane = tid & 31;

    // --- inline softmax over the 196 scores of batch b ---
    float v0 = g_scores[(size_t)b * Sx + tid];
    if (mask[(size_t)b * Sx + tid]) v0 = -100000000.0f;
    float v1 = -INFINITY;
    if (tid < Sx - 128) {
        v1 = g_scores[(size_t)b * Sx + tid + 128];
        if (mask[(size_t)b * Sx + tid + 128]) v1 = -100000000.0f;
    }
    float m = fmaxf(v0, v1);
#pragma unroll
    for (int o = 16; o > 0; o >>= 1) m = fmaxf(m, __shfl_xor_sync(0xffffffffu, m, o));
    if (lane == 0) red[warp] = m;
    __syncthreads();
    float smax = fmaxf(fmaxf(red[0], red[1]), fmaxf(red[2], red[3]));

    float e0 = __expf(v0 - smax);
    float e1 = (tid < Sx - 128) ? __expf(v1 - smax) : 0.f;
    float ssum = e0 + e1;
#pragma unroll
    for (int o = 16; o > 0; o >>= 1) ssum += __shfl_xor_sync(0xffffffffu, ssum, o);
    if (lane == 0) red[warp + 4] = ssum;
    __syncthreads();
    float inv = 1.0f / (red[4] + red[5] + red[6] + red[7]);
    sw[tid] = e0 * inv;
    if (tid < Sx - 128) sw[tid + 128] = e1 * inv;
    __syncthreads();

    // --- weighted sum over att_feats ---
    const float4* base = reinterpret_cast<const float4*>(att_feats + (size_t)b * Sx * Rx)
                         + blockIdx.x * 128 + tid;
    float4 acc = make_float4(0.f, 0.f, 0.f, 0.f);
#pragma unroll 2
    for (int s0 = 0; s0 < 192; s0 += 8) {
        float4 v[8];
#pragma unroll
        for (int u = 0; u < 8; u++)
            v[u] = __ldcs(&base[(size_t)(s0 + u) * (Rx / 4)]);
#pragma unroll
        for (int u = 0; u < 8; u++) {
            float w = sw[s0 + u];
            acc.x += w * v[u].x;
            acc.y += w * v[u].y;
            acc.z += w * v[u].z;
            acc.w += w * v[u].w;
        }
    }
#pragma unroll
    for (int s = 192; s < Sx; s++) {
        float w = sw[s];
        float4 v = __ldcs(&base[(size_t)s * (Rx / 4)]);
        acc.x += w * v.x;
        acc.y += w * v.y;
        acc.z += w * v.z;
        acc.w += w * v.w;
    }
    reinterpret_cast<float4*>(out + (size_t)b * Rx)[blockIdx.x * 128 + tid] = acc;
}

// ---------------------------------------------------------------------------
extern "C" void kernel_launch(void* const* d_in, const int* in_sizes, int n_in,
                              void* d_out, int out_size) {
    const float*         h         = (const float*)d_in[0];
    const float*         att_feats = (const float*)d_in[1];
    const float*         p_att     = (const float*)d_in[2];
    const unsigned char* mask      = (const unsigned char*)d_in[3];
    const float*         W_h       = (const float*)d_in[4];
    const float*         b_h       = (const float*)d_in[5];
    const float*         W_a       = (const float*)d_in[6];
    const float*         b_a       = (const float*)d_in[7];
    float*               out       = (float*)d_out;

    k_gemm<<<dim3(Ax / 64, Bx / 128, NSPLIT), 256>>>(h, W_h);
    k_scores_raw<<<dim3(4, Bx), 256>>>(p_att, W_a, b_a, b_h);
    k_wsum<<<dim3(4, Bx), 128>>>(att_feats, mask, out);
}

// round 7
// speedup vs baseline: 1.5029x; 1.0003x over previous
#include <cuda_runtime.h>
#include <math.h>

#define Bx 256
#define Sx 196
#define Rx 2048
#define Ax 512
#define NSPLIT 16
#define KCHUNK (Rx / NSPLIT)  // 128
#define SCHUNK 49             // rows per score block (4 blocks per batch)

// p_att prefetch geometry: 256*196*512*4 B = 802816 lines of 128B.
// 256 gemm CTAs x 3136 lines each; 8 k-steps x 392 lines per step.
#define PF_LINES_PER_CTA 3136
#define PF_LINES_PER_STEP 392

// Scratch (allocation-free rule: __device__ globals)
__device__ float g_part[NSPLIT * Bx * Ax];   // 8 MB split-K partials
__device__ float g_scores[Bx * Sx];          // 200 KB raw scores

// Fast tanh: MUFU.EX2 + MUFU.RCP + FMA. ~1e-7 rel err.
__device__ __forceinline__ float fast_tanh(float x) {
    float ax = fabsf(x);
    float e = __expf(2.0f * ax);
    float r;
    asm("rcp.approx.f32 %0, %1;" : "=f"(r) : "f"(e + 1.0f));
    r = fmaf(-2.0f, r, 1.0f);
    return copysignf(r, x);
}

// ---------------------------------------------------------------------------
// K1: att_h partials = h[B,R] @ W_h[R,A], split-K over z.
// BM=128 BN=64 BK=16, 256 threads, 8x4 tile, double-buffered smem,
// one barrier per K-step. Additionally prefetches p_att into L2 (uses the
// idle HBM bandwidth under the compute-bound GEMM) so k_scores_raw reads
// L2-resident data.
// ---------------------------------------------------------------------------
__global__ __launch_bounds__(256)
void k_gemm(const float* __restrict__ h, const float* __restrict__ Wh,
            const float* __restrict__ p_att) {
    const int BM = 128, BN = 64, BK = 16;
    __shared__ float As[2][BK][BM + 4];
    __shared__ float Bs[2][BK][BN];

    int tid = threadIdx.x;
    int tx = tid & 15;
    int ty = tid >> 4;
    int bm = blockIdx.y * BM;
    int bn = blockIdx.x * BN;
    int kc0 = blockIdx.z * KCHUNK;

    // linear CTA id 0..255 for prefetch slicing
    int cta = blockIdx.x + blockIdx.y * 8 + blockIdx.z * 16;
    const char* pf_base = reinterpret_cast<const char*>(p_att)
                        + (size_t)cta * PF_LINES_PER_CTA * 128;

    float acc[8][4];
#pragma unroll
    for (int i = 0; i < 8; i++)
#pragma unroll
        for (int j = 0; j < 4; j++) acc[i][j] = 0.f;

    float pa[8], pb[4];
#pragma unroll
    for (int j = 0; j < 8; j++) {
        int lin = tid + 256 * j;
        pa[j] = h[(size_t)(bm + (lin >> 4)) * Rx + kc0 + (lin & 15)];
    }
#pragma unroll
    for (int j = 0; j < 4; j++) {
        int lin = tid + 256 * j;
        pb[j] = Wh[(size_t)(kc0 + (lin >> 6)) * Ax + bn + (lin & 63)];
    }

    const int NT = KCHUNK / BK;  // 8
#pragma unroll
    for (int t = 0; t < NT; t++) {
        int cur = t & 1;
#pragma unroll
        for (int j = 0; j < 8; j++) {
            int lin = tid + 256 * j;
            As[cur][lin & 15][lin >> 4] = pa[j];
        }
#pragma unroll
        for (int j = 0; j < 4; j++) {
            int lin = tid + 256 * j;
            Bs[cur][lin >> 6][lin & 63] = pb[j];
        }
        __syncthreads();

        // prefetch this CTA's p_att slice into L2 (392 lines per k-step)
        {
            const char* p0 = pf_base + (size_t)t * PF_LINES_PER_STEP * 128;
            asm volatile("prefetch.global.L2 [%0];" :: "l"(p0 + (size_t)tid * 128));
            if (tid < PF_LINES_PER_STEP - 256)
                asm volatile("prefetch.global.L2 [%0];" :: "l"(p0 + (size_t)(tid + 256) * 128));
        }

        if (t < NT - 1) {
            int kc = kc0 + (t + 1) * BK;
#pragma unroll
            for (int j = 0; j < 8; j++) {
                int lin = tid + 256 * j;
                pa[j] = h[(size_t)(bm + (lin >> 4)) * Rx + kc + (lin & 15)];
            }
#pragma unroll
            for (int j = 0; j < 4; j++) {
                int lin = tid + 256 * j;
                pb[j] = Wh[(size_t)(kc + (lin >> 6)) * Ax + bn + (lin & 63)];
            }
        }

#pragma unroll
        for (int kk = 0; kk < BK; kk++) {
            float4 a0 = *reinterpret_cast<const float4*>(&As[cur][kk][ty * 8]);
            float4 a1 = *reinterpret_cast<const float4*>(&As[cur][kk][ty * 8 + 4]);
            float4 b4 = *reinterpret_cast<const float4*>(&Bs[cur][kk][tx * 4]);
            float av[8] = {a0.x, a0.y, a0.z, a0.w, a1.x, a1.y, a1.z, a1.w};
            float bv[4] = {b4.x, b4.y, b4.z, b4.w};
#pragma unroll
            for (int i = 0; i < 8; i++)
#pragma unroll
                for (int j = 0; j < 4; j++)
                    acc[i][j] += av[i] * bv[j];
        }
    }

    float* out = g_part + (size_t)blockIdx.z * Bx * Ax;
#pragma unroll
    for (int i = 0; i < 8; i++) {
        int m = bm + ty * 8 + i;
        float4 v = make_float4(acc[i][0], acc[i][1], acc[i][2], acc[i][3]);
        *reinterpret_cast<float4*>(&out[(size_t)m * Ax + bn + tx * 4]) = v;
    }
}

// ---------------------------------------------------------------------------
// K2: raw scores. grid (4, B): block q handles 49 rows of batch b.
// att_h reduced inline from split-K partials (+ b_h). p_att now L2-resident.
// ---------------------------------------------------------------------------
__global__ __launch_bounds__(256)
void k_scores_raw(const float* __restrict__ p_att,
                  const float* __restrict__ W_a,
                  const float* __restrict__ b_a,
                  const float* __restrict__ b_h) {
    int b = blockIdx.y;
    int q = blockIdx.x;
    __shared__ float sh_ah[Ax];
    __shared__ float sh_wa[Ax];

    int tid = threadIdx.x;
#pragma unroll
    for (int e = 0; e < 2; e++) {
        int a = tid + 256 * e;
        float v = b_h[a];
#pragma unroll
        for (int z = 0; z < NSPLIT; z++)
            v += g_part[(size_t)z * Bx * Ax + (size_t)b * Ax + a];
        sh_ah[a] = v;
        sh_wa[a] = W_a[a];
    }
    __syncthreads();

    int warp = tid >> 5, lane = tid & 31;
    float ba = b_a[0];
    int s_end = (q + 1) * SCHUNK;
    if (s_end > Sx) s_end = Sx;

    for (int s = q * SCHUNK + warp; s < s_end; s += 8) {
        const float4* p = reinterpret_cast<const float4*>(p_att + ((size_t)b * Sx + s) * Ax);
        float acc = 0.f;
#pragma unroll
        for (int i = 0; i < 4; i++) {
            float4 v  = __ldcs(&p[lane + 32 * i]);
            float4 ah = reinterpret_cast<const float4*>(sh_ah)[lane + 32 * i];
            float4 wa = reinterpret_cast<const float4*>(sh_wa)[lane + 32 * i];
            acc += fast_tanh(v.x + ah.x) * wa.x;
            acc += fast_tanh(v.y + ah.y) * wa.y;
            acc += fast_tanh(v.z + ah.z) * wa.z;
            acc += fast_tanh(v.w + ah.w) * wa.w;
        }
#pragma unroll
        for (int o = 16; o > 0; o >>= 1) acc += __shfl_xor_sync(0xffffffffu, acc, o);
        if (lane == 0) g_scores[(size_t)b * Sx + s] = acc + ba;
    }
}

// ---------------------------------------------------------------------------
// K3: softmax (redundant per block, L2-resident) + weighted sum.
// grid (4, B), 128 threads. HBM streaming with __ldcs + unroll 8.
// ---------------------------------------------------------------------------
__global__ __launch_bounds__(128)
void k_wsum(const float* __restrict__ att_feats,
            const unsigned char* __restrict__ mask,
            float* __restrict__ out) {
    int b = blockIdx.y;
    int tid = threadIdx.x;  // 0..127
    __shared__ float sw[Sx];
    __shared__ float red[8];
    int warp = tid >> 5, lane = tid & 31;

    float v0 = g_scores[(size_t)b * Sx + tid];
    if (mask[(size_t)b * Sx + tid]) v0 = -100000000.0f;
    float v1 = -INFINITY;
    if (tid < Sx - 128) {
        v1 = g_scores[(size_t)b * Sx + tid + 128];
        if (mask[(size_t)b * Sx + tid + 128]) v1 = -100000000.0f;
    }
    float m = fmaxf(v0, v1);
#pragma unroll
    for (int o = 16; o > 0; o >>= 1) m = fmaxf(m, __shfl_xor_sync(0xffffffffu, m, o));
    if (lane == 0) red[warp] = m;
    __syncthreads();
    float smax = fmaxf(fmaxf(red[0], red[1]), fmaxf(red[2], red[3]));

    float e0 = __expf(v0 - smax);
    float e1 = (tid < Sx - 128) ? __expf(v1 - smax) : 0.f;
    float ssum = e0 + e1;
#pragma unroll
    for (int o = 16; o > 0; o >>= 1) ssum += __shfl_xor_sync(0xffffffffu, ssum, o);
    if (lane == 0) red[warp + 4] = ssum;
    __syncthreads();
    float inv = 1.0f / (red[4] + red[5] + red[6] + red[7]);
    sw[tid] = e0 * inv;
    if (tid < Sx - 128) sw[tid + 128] = e1 * inv;
    __syncthreads();

    const float4* base = reinterpret_cast<const float4*>(att_feats + (size_t)b * Sx * Rx)
                         + blockIdx.x * 128 + tid;
    float4 acc = make_float4(0.f, 0.f, 0.f, 0.f);
#pragma unroll 2
    for (int s0 = 0; s0 < 192; s0 += 8) {
        float4 v[8];
#pragma unroll
        for (int u = 0; u < 8; u++)
            v[u] = __ldcs(&base[(size_t)(s0 + u) * (Rx / 4)]);
#pragma unroll
        for (int u = 0; u < 8; u++) {
            float w = sw[s0 + u];
            acc.x += w * v[u].x;
            acc.y += w * v[u].y;
            acc.z += w * v[u].z;
            acc.w += w * v[u].w;
        }
    }
#pragma unroll
    for (int s = 192; s < Sx; s++) {
        float w = sw[s];
        float4 v = __ldcs(&base[(size_t)s * (Rx / 4)]);
        acc.x += w * v.x;
        acc.y += w * v.y;
        acc.z += w * v.z;
        acc.w += w * v.w;
    }
    reinterpret_cast<float4*>(out + (size_t)b * Rx)[blockIdx.x * 128 + tid] = acc;
}

// ---------------------------------------------------------------------------
extern "C" void kernel_launch(void* const* d_in, const int* in_sizes, int n_in,
                              void* d_out, int out_size) {
    const float*         h         = (const float*)d_in[0];
    const float*         att_feats = (const float*)d_in[1];
    const float*         p_att     = (const float*)d_in[2];
    const unsigned char* mask      = (const unsigned char*)d_in[3];
    const float*         W_h       = (const float*)d_in[4];
    const float*         b_h       = (const float*)d_in[5];
    const float*         W_a       = (const float*)d_in[6];
    const float*         b_a       = (const float*)d_in[7];
    float*               out       = (float*)d_out;

    k_gemm<<<dim3(Ax / 64, Bx / 128, NSPLIT), 256>>>(h, W_h, p_att);
    k_scores_raw<<<dim3(4, Bx), 256>>>(p_att, W_a, b_a, b_h);
    k_wsum<<<dim3(4, Bx), 128>>>(att_feats, mask, out);
}